// round 1
// baseline (speedup 1.0000x reference)
#include <cuda_runtime.h>
#include <cuda_bf16.h>
#include <stdint.h>

// Problem constants (D, H are fixed by the model; N, E derived from in_sizes)
#define DD 512
#define HH 8
#define MAXN 50048
#define LN_EPS 1e-5f

// ---------------- scratch (device globals; no allocation allowed) -------------
__device__ __align__(16) float g_deg [MAXN];
__device__ __align__(16) float g_dinv[MAXN];
__device__ __align__(16) float g_u   [MAXN * HH];   // (x@W1)*dinv
__device__ __align__(16) float g_agg1[MAXN * HH];
__device__ __align__(16) float g_v   [MAXN * HH];   // relu(LN(...))*dinv
__device__ __align__(16) float g_agg2[MAXN * HH];
__device__ int g_is64;

// ---------------- helpers ------------------------------------------------------
__device__ __forceinline__ void red_add_v4(float* addr, float4 v) {
    asm volatile("red.global.add.v4.f32 [%0], {%1,%2,%3,%4};"
                 :: "l"(addr), "f"(v.x), "f"(v.y), "f"(v.z), "f"(v.w)
                 : "memory");
}

__device__ __forceinline__ int load_idx(const int* __restrict__ ei, int is64,
                                        long long flat) {
    // int64 little-endian: value fits in low 32 bits (indices < N < 2^31)
    return is64 ? ((const int2*)ei)[flat].x : ei[flat];
}

// ---------------- kernels ------------------------------------------------------

// Detect whether edge_index arrived as int64 (jax x64 on) or int32 (x64 off).
// If int64: the high 32-bit word of every element is 0. If int32: words at odd
// positions are random indices in [0,N) -> virtually impossible all zero.
__global__ void k_detect(const int* __restrict__ ei, int E) {
    if (threadIdx.x == 0 && blockIdx.x == 0) {
        int f = 1;
        int lim = 2 * E < 256 ? 2 * E : 256;
        for (int i = 1; i < lim; i += 2)
            if (ei[i] != 0) { f = 0; break; }
        g_is64 = f;
    }
}

__global__ void k_initdeg(int N) {
    int i = blockIdx.x * blockDim.x + threadIdx.x;
    if (i < N) g_deg[i] = 1.0f;   // self-loop
}

__global__ void k_deg(const int* __restrict__ ei, int E) {
    int e = blockIdx.x * blockDim.x + threadIdx.x;
    if (e >= E) return;
    int is64 = g_is64;
    int dst = load_idx(ei, is64, (long long)E + e);
    atomicAdd(&g_deg[dst], 1.0f);
}

__global__ void k_dinv(int N) {
    int i = blockIdx.x * blockDim.x + threadIdx.x;
    if (i < N) g_dinv[i] = rsqrtf(g_deg[i]);
}

// u[i] = (x[i] @ W1) * dinv[i]; agg1[i] seeded with u[i] (self-loop term).
// One thread per node; x tiles staged through shared memory for coalescing.
__global__ void k_gemm1(const float* __restrict__ x,
                        const float* __restrict__ W1, int N) {
    __shared__ float sW1[DD * HH];        // 16 KB
    __shared__ float sx[128 * 33];        // padded tile, conflict-free
    const int tid = threadIdx.x;
    const int node0 = blockIdx.x * 128;
    const int node = node0 + tid;

    for (int i = tid; i < DD * HH; i += 128) sW1[i] = W1[i];

    float acc[HH];
#pragma unroll
    for (int h = 0; h < HH; h++) acc[h] = 0.f;

    for (int kb = 0; kb < DD; kb += 32) {
        __syncthreads();
        // stage 128 rows x 32 cols, coalesced
#pragma unroll
        for (int it = 0; it < 32; it++) {
            int f = tid + it * 128;
            int r = f >> 5, c = f & 31;
            int n = node0 + r;
            sx[r * 33 + c] = (n < N) ? x[(size_t)n * DD + kb + c] : 0.f;
        }
        __syncthreads();
#pragma unroll 8
        for (int c = 0; c < 32; c++) {
            float xv = sx[tid * 33 + c];
            const float4* w = (const float4*)&sW1[(kb + c) * HH];
            float4 wa = w[0], wb = w[1];
            acc[0] = fmaf(xv, wa.x, acc[0]);
            acc[1] = fmaf(xv, wa.y, acc[1]);
            acc[2] = fmaf(xv, wa.z, acc[2]);
            acc[3] = fmaf(xv, wa.w, acc[3]);
            acc[4] = fmaf(xv, wb.x, acc[4]);
            acc[5] = fmaf(xv, wb.y, acc[5]);
            acc[6] = fmaf(xv, wb.z, acc[6]);
            acc[7] = fmaf(xv, wb.w, acc[7]);
        }
    }
    if (node < N) {
        float di = g_dinv[node];
        float4 o0 = make_float4(acc[0]*di, acc[1]*di, acc[2]*di, acc[3]*di);
        float4 o1 = make_float4(acc[4]*di, acc[5]*di, acc[6]*di, acc[7]*di);
        ((float4*)g_u)[node * 2]     = o0;
        ((float4*)g_u)[node * 2 + 1] = o1;
        ((float4*)g_agg1)[node * 2]     = o0;   // self-loop seed
        ((float4*)g_agg1)[node * 2 + 1] = o1;
    }
}

// Edge scatter in H=8 space: agg[dst] += u[src]  (vector red, 2x16B per edge)
template <int PHASE>
__global__ void k_agg(const int* __restrict__ ei, int E) {
    int e = blockIdx.x * blockDim.x + threadIdx.x;
    if (e >= E) return;
    int is64 = g_is64;
    int src = load_idx(ei, is64, e);
    int dst = load_idx(ei, is64, (long long)E + e);
    const float* u = (PHASE == 0) ? g_u : g_v;
    float*     agg = (PHASE == 0) ? g_agg1 : g_agg2;
    float4 a = __ldg((const float4*)(u + (size_t)src * HH));
    float4 b = __ldg((const float4*)(u + (size_t)src * HH) + 1);
    red_add_v4(agg + (size_t)dst * HH,     a);
    red_add_v4(agg + (size_t)dst * HH + 4, b);
}

// Fused: h1 = agg1*dinv + b1; LayerNorm(H=8); *gamma+beta; relu; v = hn*dinv;
// seed agg2 with v (self-loop).
__global__ void k_ln(const float* __restrict__ b1,
                     const float* __restrict__ gamma,
                     const float* __restrict__ beta, int N) {
    int i = blockIdx.x * blockDim.x + threadIdx.x;
    if (i >= N) return;
    float di = g_dinv[i];
    float4 p0 = ((const float4*)g_agg1)[i * 2];
    float4 p1 = ((const float4*)g_agg1)[i * 2 + 1];
    float h[HH] = {p0.x, p0.y, p0.z, p0.w, p1.x, p1.y, p1.z, p1.w};
    float mu = 0.f;
#pragma unroll
    for (int k = 0; k < HH; k++) { h[k] = h[k] * di + __ldg(&b1[k]); mu += h[k]; }
    mu *= 0.125f;
    float var = 0.f;
#pragma unroll
    for (int k = 0; k < HH; k++) { float d = h[k] - mu; var += d * d; }
    var *= 0.125f;
    float r = rsqrtf(var + LN_EPS);
    float v[HH];
#pragma unroll
    for (int k = 0; k < HH; k++) {
        float hn = (h[k] - mu) * r * __ldg(&gamma[k]) + __ldg(&beta[k]);
        v[k] = fmaxf(hn, 0.f) * di;
    }
    float4 o0 = make_float4(v[0], v[1], v[2], v[3]);
    float4 o1 = make_float4(v[4], v[5], v[6], v[7]);
    ((float4*)g_v)[i * 2]     = o0;
    ((float4*)g_v)[i * 2 + 1] = o1;
    ((float4*)g_agg2)[i * 2]     = o0;   // self-loop seed
    ((float4*)g_agg2)[i * 2 + 1] = o1;
}

// out[i] = relu((agg2[i]*dinv[i]) @ W2 + b2) * sf[i]; warp per node.
__global__ void k_out(const float* __restrict__ W2,
                      const float* __restrict__ b2,
                      const float* __restrict__ sf,
                      float* __restrict__ out, int N) {
    __shared__ float sW2[HH * DD];   // 16 KB
    __shared__ float sb2[DD];        // 2 KB
    const int tid = threadIdx.x;
    for (int i = tid; i < HH * DD; i += 256) sW2[i] = W2[i];
    for (int i = tid; i < DD; i += 256) sb2[i] = b2[i];
    __syncthreads();

    const int warp = tid >> 5, lane = tid & 31;
    const int node = blockIdx.x * 8 + warp;
    if (node >= N) return;

    float di = g_dinv[node];
    float myv = g_agg2[(size_t)node * HH + (lane & 7)] * di;
    float a[HH];
#pragma unroll
    for (int h = 0; h < HH; h++) a[h] = __shfl_sync(0xffffffffu, myv, h);
    float s = sf[node];

#pragma unroll
    for (int j = 0; j < 4; j++) {
        int d4 = lane + 32 * j;                   // float4 column index
        float4 acc = ((const float4*)sb2)[d4];
#pragma unroll
        for (int h = 0; h < HH; h++) {
            float4 w = ((const float4*)sW2)[h * (DD / 4) + d4];
            acc.x = fmaf(a[h], w.x, acc.x);
            acc.y = fmaf(a[h], w.y, acc.y);
            acc.z = fmaf(a[h], w.z, acc.z);
            acc.w = fmaf(a[h], w.w, acc.w);
        }
        acc.x = fmaxf(acc.x, 0.f) * s;
        acc.y = fmaxf(acc.y, 0.f) * s;
        acc.z = fmaxf(acc.z, 0.f) * s;
        acc.w = fmaxf(acc.w, 0.f) * s;
        ((float4*)out)[(size_t)node * (DD / 4) + d4] = acc;
    }
}

// ---------------- launch -------------------------------------------------------
extern "C" void kernel_launch(void* const* d_in, const int* in_sizes, int n_in,
                              void* d_out, int out_size) {
    const float* x     = (const float*)d_in[0];
    const float* sf    = (const float*)d_in[1];
    const float* W1    = (const float*)d_in[2];
    const float* b1    = (const float*)d_in[3];
    const float* gamma = (const float*)d_in[4];
    const float* beta  = (const float*)d_in[5];
    const float* W2    = (const float*)d_in[6];
    const float* b2    = (const float*)d_in[7];
    const int*   ei    = (const int*)d_in[8];
    float* out = (float*)d_out;

    int N = in_sizes[0] / DD;
    int E = in_sizes[8] / 2;
    if (N > MAXN) N = MAXN;   // safety clamp (problem has N=50000)

    const int TB = 256;
    k_detect <<<1, 32>>>(ei, E);
    k_initdeg<<<(N + TB - 1) / TB, TB>>>(N);
    k_deg    <<<(E + TB - 1) / TB, TB>>>(ei, E);
    k_dinv   <<<(N + TB - 1) / TB, TB>>>(N);
    k_gemm1  <<<(N + 127) / 128, 128>>>(x, W1, N);
    k_agg<0> <<<(E + TB - 1) / TB, TB>>>(ei, E);
    k_ln     <<<(N + TB - 1) / TB, TB>>>(b1, gamma, beta, N);
    k_agg<1> <<<(E + TB - 1) / TB, TB>>>(ei, E);
    k_out    <<<(N + 7) / 8, 256>>>(W2, b2, sf, out, N);
}

// round 2
// speedup vs baseline: 1.0134x; 1.0134x over previous
#include <cuda_runtime.h>
#include <cuda_bf16.h>
#include <stdint.h>

#define DD 512
#define HH 8
#define MAXN 50048
#define MAXE 800000
#define LN_EPS 1e-5f

// ---------------- scratch (device globals) -------------------------------------
__device__ __align__(16) float g_deg [MAXN];
__device__ __align__(16) float g_u   [MAXN * HH];   // (x@W1)*dinv
__device__ __align__(16) float g_agg1[MAXN * HH];
__device__ __align__(16) float g_v   [MAXN * HH];   // relu(LN(...))*dinv
__device__ __align__(16) float g_agg2[MAXN * HH];
__device__ __align__(16) int2  g_edge[MAXE];        // packed (src,dst) int32
__device__ int g_is64;

// ---------------- helpers ------------------------------------------------------
__device__ __forceinline__ void red_add_v4(float* addr, float4 v) {
    asm volatile("red.global.add.v4.f32 [%0], {%1,%2,%3,%4};"
                 :: "l"(addr), "f"(v.x), "f"(v.y), "f"(v.z), "f"(v.w)
                 : "memory");
}

// ---------------- kernels ------------------------------------------------------

// deg=1 init (self-loop) + int64/int32 detection (block 0, thread 0).
// int64 little-endian: high words of indices < 2^31 are all zero; int32 edge
// data at odd word positions is a random index -> virtually never all zero.
__global__ void k_init(const int* __restrict__ ei, int E, int N) {
    int i = blockIdx.x * blockDim.x + threadIdx.x;
    if (i < N) g_deg[i] = 1.0f;
    if (i == 0) {
        int f = 1;
        int lim = 2 * E < 256 ? 2 * E : 256;
        for (int w = 1; w < lim; w += 2)
            if (ei[w] != 0) { f = 0; break; }
        g_is64 = f;
    }
}

// Decode edge_index once: pack to int2, count in-degrees.
__global__ void k_prep(const int* __restrict__ ei, int E) {
    int e = blockIdx.x * blockDim.x + threadIdx.x;
    if (e >= E) return;
    int src, dst;
    if (g_is64) {
        src = ((const int2*)ei)[e].x;
        dst = ((const int2*)ei)[(size_t)E + e].x;
    } else {
        src = ei[e];
        dst = ei[E + e];
    }
    g_edge[e] = make_int2(src, dst);
    atomicAdd(&g_deg[dst], 1.0f);
}

// u[i] = (x[i] @ W1) * rsqrt(deg[i]); agg1[i] seeded with u[i] (self-loop).
__global__ void k_gemm1(const float* __restrict__ x,
                        const float* __restrict__ W1, int N) {
    __shared__ float sW1[DD * HH];        // 16 KB
    __shared__ float sx[128 * 33];        // padded, conflict-free reads
    const int tid = threadIdx.x;
    const int node0 = blockIdx.x * 128;
    const int node = node0 + tid;

    for (int i = tid; i < DD * HH; i += 128) sW1[i] = W1[i];

    float acc[HH];
#pragma unroll
    for (int h = 0; h < HH; h++) acc[h] = 0.f;

    for (int kb = 0; kb < DD; kb += 32) {
        __syncthreads();
#pragma unroll
        for (int it = 0; it < 32; it++) {
            int f = tid + it * 128;
            int r = f >> 5, c = f & 31;
            int n = node0 + r;
            sx[r * 33 + c] = (n < N) ? x[(size_t)n * DD + kb + c] : 0.f;
        }
        __syncthreads();
#pragma unroll 8
        for (int c = 0; c < 32; c++) {
            float xv = sx[tid * 33 + c];
            const float4* w = (const float4*)&sW1[(kb + c) * HH];
            float4 wa = w[0], wb = w[1];
            acc[0] = fmaf(xv, wa.x, acc[0]);
            acc[1] = fmaf(xv, wa.y, acc[1]);
            acc[2] = fmaf(xv, wa.z, acc[2]);
            acc[3] = fmaf(xv, wa.w, acc[3]);
            acc[4] = fmaf(xv, wb.x, acc[4]);
            acc[5] = fmaf(xv, wb.y, acc[5]);
            acc[6] = fmaf(xv, wb.z, acc[6]);
            acc[7] = fmaf(xv, wb.w, acc[7]);
        }
    }
    if (node < N) {
        float di = rsqrtf(g_deg[node]);
        float4 o0 = make_float4(acc[0]*di, acc[1]*di, acc[2]*di, acc[3]*di);
        float4 o1 = make_float4(acc[4]*di, acc[5]*di, acc[6]*di, acc[7]*di);
        ((float4*)g_u)[node * 2]     = o0;
        ((float4*)g_u)[node * 2 + 1] = o1;
        ((float4*)g_agg1)[node * 2]     = o0;   // self-loop seed
        ((float4*)g_agg1)[node * 2 + 1] = o1;
    }
}

// Edge scatter in H=8 space: agg[dst] += u[src]. 2 edges/thread via int4.
template <int PHASE>
__global__ void k_agg(int E) {
    int t = blockIdx.x * blockDim.x + threadIdx.x;
    int e0 = t * 2;
    if (e0 >= E) return;
    const float* __restrict__ u = (PHASE == 0) ? g_u : g_v;
    float*                  agg = (PHASE == 0) ? g_agg1 : g_agg2;

    int4 p = *(const int4*)&g_edge[e0];    // edges e0 (x,y) and e0+1 (z,w)
    // gather both sources first (MLP), then scatter
    float4 a0 = __ldg((const float4*)(u + (size_t)p.x * HH));
    float4 a1 = __ldg((const float4*)(u + (size_t)p.x * HH) + 1);
    if (e0 + 1 < E) {
        float4 b0 = __ldg((const float4*)(u + (size_t)p.z * HH));
        float4 b1 = __ldg((const float4*)(u + (size_t)p.z * HH) + 1);
        red_add_v4(agg + (size_t)p.y * HH,     a0);
        red_add_v4(agg + (size_t)p.y * HH + 4, a1);
        red_add_v4(agg + (size_t)p.w * HH,     b0);
        red_add_v4(agg + (size_t)p.w * HH + 4, b1);
    } else {
        red_add_v4(agg + (size_t)p.y * HH,     a0);
        red_add_v4(agg + (size_t)p.y * HH + 4, a1);
    }
}

// Fused: h1 = agg1*dinv + b1; LN(H=8); affine; relu; v = hn*dinv; seed agg2.
__global__ void k_ln(const float* __restrict__ b1,
                     const float* __restrict__ gamma,
                     const float* __restrict__ beta, int N) {
    int i = blockIdx.x * blockDim.x + threadIdx.x;
    if (i >= N) return;
    float di = rsqrtf(g_deg[i]);
    float4 p0 = ((const float4*)g_agg1)[i * 2];
    float4 p1 = ((const float4*)g_agg1)[i * 2 + 1];
    float h[HH] = {p0.x, p0.y, p0.z, p0.w, p1.x, p1.y, p1.z, p1.w};
    float mu = 0.f;
#pragma unroll
    for (int k = 0; k < HH; k++) { h[k] = h[k] * di + __ldg(&b1[k]); mu += h[k]; }
    mu *= 0.125f;
    float var = 0.f;
#pragma unroll
    for (int k = 0; k < HH; k++) { float d = h[k] - mu; var += d * d; }
    var *= 0.125f;
    float r = rsqrtf(var + LN_EPS);
    float v[HH];
#pragma unroll
    for (int k = 0; k < HH; k++) {
        float hn = (h[k] - mu) * r * __ldg(&gamma[k]) + __ldg(&beta[k]);
        v[k] = fmaxf(hn, 0.f) * di;
    }
    float4 o0 = make_float4(v[0], v[1], v[2], v[3]);
    float4 o1 = make_float4(v[4], v[5], v[6], v[7]);
    ((float4*)g_v)[i * 2]     = o0;
    ((float4*)g_v)[i * 2 + 1] = o1;
    ((float4*)g_agg2)[i * 2]     = o0;   // self-loop seed
    ((float4*)g_agg2)[i * 2 + 1] = o1;
}

// out[i] = relu((agg2[i]*dinv[i]) @ W2 + b2) * sf[i]; warp per node.
__global__ void k_out(const float* __restrict__ W2,
                      const float* __restrict__ b2,
                      const float* __restrict__ sf,
                      float* __restrict__ out, int N) {
    __shared__ float sW2[HH * DD];   // 16 KB
    __shared__ float sb2[DD];        // 2 KB
    const int tid = threadIdx.x;
    for (int i = tid; i < HH * DD; i += 256) sW2[i] = W2[i];
    for (int i = tid; i < DD; i += 256) sb2[i] = b2[i];
    __syncthreads();

    const int warp = tid >> 5, lane = tid & 31;
    const int node = blockIdx.x * 8 + warp;
    if (node >= N) return;

    float di = rsqrtf(g_deg[node]);
    float myv = g_agg2[(size_t)node * HH + (lane & 7)] * di;
    float a[HH];
#pragma unroll
    for (int h = 0; h < HH; h++) a[h] = __shfl_sync(0xffffffffu, myv, h);
    float s = sf[node];

#pragma unroll
    for (int j = 0; j < 4; j++) {
        int d4 = lane + 32 * j;
        float4 acc = ((const float4*)sb2)[d4];
#pragma unroll
        for (int h = 0; h < HH; h++) {
            float4 w = ((const float4*)sW2)[h * (DD / 4) + d4];
            acc.x = fmaf(a[h], w.x, acc.x);
            acc.y = fmaf(a[h], w.y, acc.y);
            acc.z = fmaf(a[h], w.z, acc.z);
            acc.w = fmaf(a[h], w.w, acc.w);
        }
        acc.x = fmaxf(acc.x, 0.f) * s;
        acc.y = fmaxf(acc.y, 0.f) * s;
        acc.z = fmaxf(acc.z, 0.f) * s;
        acc.w = fmaxf(acc.w, 0.f) * s;
        ((float4*)out)[(size_t)node * (DD / 4) + d4] = acc;
    }
}

// ---------------- launch -------------------------------------------------------
extern "C" void kernel_launch(void* const* d_in, const int* in_sizes, int n_in,
                              void* d_out, int out_size) {
    const float* x     = (const float*)d_in[0];
    const float* sf    = (const float*)d_in[1];
    const float* W1    = (const float*)d_in[2];
    const float* b1    = (const float*)d_in[3];
    const float* gamma = (const float*)d_in[4];
    const float* beta  = (const float*)d_in[5];
    const float* W2    = (const float*)d_in[6];
    const float* b2    = (const float*)d_in[7];
    const int*   ei    = (const int*)d_in[8];
    float* out = (float*)d_out;

    int N = in_sizes[0] / DD;
    int E = in_sizes[8] / 2;
    if (N > MAXN) N = MAXN;
    if (E > MAXE) E = MAXE;

    const int TB = 256;
    k_init   <<<(N + TB - 1) / TB, TB>>>(ei, E, N);
    k_prep   <<<(E + TB - 1) / TB, TB>>>(ei, E);
    k_gemm1  <<<(N + 127) / 128, 128>>>(x, W1, N);
    k_agg<0> <<<(E / 2 + TB - 1) / TB, TB>>>(E);
    k_ln     <<<(N + TB - 1) / TB, TB>>>(b1, gamma, beta, N);
    k_agg<1> <<<(E / 2 + TB - 1) / TB, TB>>>(E);
    k_out    <<<(N + 7) / 8, 256>>>(W2, b2, sf, out, N);
}

// round 4
// speedup vs baseline: 1.2744x; 1.2575x over previous
#include <cuda_runtime.h>
#include <stdint.h>

#define DD 512
#define HH 8
#define MAXN 50048
#define MAXE 800000
#define LN_EPS 1e-5f
#define TPB 256

// ---------------- scratch (device globals; zero-initialized at load) -----------
__device__ __align__(16) int   g_degi[MAXN];     // invariant: zero at call entry
__device__ __align__(16) float g_u   [MAXN * HH];
__device__ __align__(16) float g_agg1[MAXN * HH];
__device__ __align__(16) float g_v   [MAXN * HH];
__device__ __align__(16) float g_agg2[MAXN * HH];
__device__ __align__(16) int2  g_edge[MAXE];
__device__ unsigned g_bar;                        // monotonic, never reset

// ---------------- helpers ------------------------------------------------------
__device__ __forceinline__ void red_add_v4(float* addr, float4 v) {
    asm volatile("red.global.add.v4.f32 [%0], {%1,%2,%3,%4};"
                 :: "l"(addr), "f"(v.x), "f"(v.y), "f"(v.z), "f"(v.w)
                 : "memory");
}

// Monotonic grid barrier: safe across graph replays (no reset needed).
// Entry invariant: g_bar is a multiple of nb; every block arrives exactly once.
__device__ __forceinline__ void gsync(unsigned nb) {
    __syncthreads();
    if (threadIdx.x == 0) {
        __threadfence();
        unsigned my = atomicAdd(&g_bar, 1u);
        unsigned target = my - (my % nb) + nb;
        while ((int)(*(volatile unsigned*)&g_bar - target) < 0) __nanosleep(64);
        __threadfence();
    }
    __syncthreads();
}

// ---------------- the single persistent kernel ---------------------------------
__global__ void __launch_bounds__(TPB, 4)
k_fused(const float* __restrict__ x,
        const float* __restrict__ sf,
        const float* __restrict__ W1,
        const float* __restrict__ b1,
        const float* __restrict__ gamma,
        const float* __restrict__ beta,
        const float* __restrict__ W2,
        const float* __restrict__ b2,
        const int*   __restrict__ ei,
        float* __restrict__ out,
        int N, int E, unsigned nb) {
    const int tid   = threadIdx.x;
    const int gtid  = blockIdx.x * TPB + tid;
    const int T     = gridDim.x * TPB;
    const int lane  = tid & 31;
    const int gwarp = gtid >> 5;
    const int W     = T >> 5;

    // Phase A: W1 transposed, s_w[h*DD + c] (16 KB). Phase F: W2 | b2 (18 KB).
    __shared__ float s_w[DD * HH + DD];
    __shared__ int   s_is64;

    // ---- prologue: stage W1 transposed + int64/int32 detection ----
    for (int i = tid; i < DD * HH; i += TPB) {
        int c = i >> 3, h = i & 7;           // W1 is [DD][HH] row-major
        s_w[h * DD + c] = W1[i];
    }
    if (tid == 0) {
        // int64 little-endian: high words of indices are 0. 16 random int32
        // edge values all being 0 is impossible in practice.
        int f = 1;
        int lim = 2 * E < 32 ? 2 * E : 32;
        for (int w = 1; w < lim; w += 2)
            if (ei[w] != 0) { f = 0; break; }
        s_is64 = f;
    }
    __syncthreads();

    // ================= Phase A: edge prep + raw GEMM1 (independent) ==========
    {
        const int is64 = s_is64;
        for (int e = gtid; e < E; e += T) {
            int src, dst;
            if (is64) {
                src = ((const int2*)ei)[e].x;
                dst = ((const int2*)ei)[(size_t)E + e].x;
            } else {
                src = ei[e];
                dst = ei[E + e];
            }
            g_edge[e] = make_int2(src, dst);
            atomicAdd(&g_degi[dst], 1);
        }
    }
    // raw u = x @ W1 (no dinv yet); warp per 2 nodes
    for (int n0 = gwarp * 2; n0 < N; n0 += W * 2) {
        const int  n1   = n0 + 1;
        const bool has1 = (n1 < N);
        const float* x0 = x + (size_t)n0 * DD;
        const float* x1 = x + (size_t)(has1 ? n1 : n0) * DD;
        float acc0[HH], acc1[HH];
#pragma unroll
        for (int h = 0; h < HH; h++) { acc0[h] = 0.f; acc1[h] = 0.f; }
#pragma unroll
        for (int it = 0; it < 16; it++) {
            int c = lane + it * 32;
            float xv0 = __ldcs(x0 + c);
            float xv1 = __ldcs(x1 + c);
#pragma unroll
            for (int h = 0; h < HH; h++) {
                float wv = s_w[h * DD + c];   // conflict-free scalar LDS
                acc0[h] = fmaf(xv0, wv, acc0[h]);
                acc1[h] = fmaf(xv1, wv, acc1[h]);
            }
        }
#pragma unroll
        for (int off = 16; off; off >>= 1) {
#pragma unroll
            for (int h = 0; h < HH; h++) {
                acc0[h] += __shfl_xor_sync(0xffffffffu, acc0[h], off);
                acc1[h] += __shfl_xor_sync(0xffffffffu, acc1[h], off);
            }
        }
        if (lane == 0) {
            ((float4*)g_u)[n0 * 2]     = make_float4(acc0[0], acc0[1], acc0[2], acc0[3]);
            ((float4*)g_u)[n0 * 2 + 1] = make_float4(acc0[4], acc0[5], acc0[6], acc0[7]);
        } else if (lane == 1 && has1) {
            ((float4*)g_u)[n1 * 2]     = make_float4(acc1[0], acc1[1], acc1[2], acc1[3]);
            ((float4*)g_u)[n1 * 2 + 1] = make_float4(acc1[4], acc1[5], acc1[6], acc1[7]);
        }
    }
    gsync(nb);

    // ================= Phase B: u *= dinv; seed agg1 ==========================
    for (int n = gtid; n < N; n += T) {
        float di = rsqrtf(1.0f + (float)g_degi[n]);
        float4 a = ((float4*)g_u)[n * 2];
        float4 b = ((float4*)g_u)[n * 2 + 1];
        a.x *= di; a.y *= di; a.z *= di; a.w *= di;
        b.x *= di; b.y *= di; b.z *= di; b.w *= di;
        ((float4*)g_u)[n * 2]        = a;
        ((float4*)g_u)[n * 2 + 1]    = b;
        ((float4*)g_agg1)[n * 2]     = a;   // self-loop seed
        ((float4*)g_agg1)[n * 2 + 1] = b;
    }
    gsync(nb);

    // ================= Phase C: edge scatter agg1 += u[src] ===================
    for (int e = gtid; e < E; e += T) {
        int2 p = g_edge[e];
        float4 a = __ldg((const float4*)(g_u + (size_t)p.x * HH));
        float4 b = __ldg((const float4*)(g_u + (size_t)p.x * HH) + 1);
        red_add_v4(g_agg1 + (size_t)p.y * HH,     a);
        red_add_v4(g_agg1 + (size_t)p.y * HH + 4, b);
    }
    gsync(nb);

    // ================= Phase D: bias + LN + ReLU + dinv; seed agg2 ============
    for (int n = gtid; n < N; n += T) {
        float di = rsqrtf(1.0f + (float)g_degi[n]);
        float4 p0 = ((const float4*)g_agg1)[n * 2];
        float4 p1 = ((const float4*)g_agg1)[n * 2 + 1];
        float h[HH] = {p0.x, p0.y, p0.z, p0.w, p1.x, p1.y, p1.z, p1.w};
        float mu = 0.f;
#pragma unroll
        for (int k = 0; k < HH; k++) { h[k] = h[k] * di + __ldg(&b1[k]); mu += h[k]; }
        mu *= 0.125f;
        float var = 0.f;
#pragma unroll
        for (int k = 0; k < HH; k++) { float d = h[k] - mu; var += d * d; }
        var *= 0.125f;
        float r = rsqrtf(var + LN_EPS);
        float v[HH];
#pragma unroll
        for (int k = 0; k < HH; k++) {
            float hn = (h[k] - mu) * r * __ldg(&gamma[k]) + __ldg(&beta[k]);
            v[k] = fmaxf(hn, 0.f) * di;
        }
        float4 o0 = make_float4(v[0], v[1], v[2], v[3]);
        float4 o1 = make_float4(v[4], v[5], v[6], v[7]);
        ((float4*)g_v)[n * 2]        = o0;
        ((float4*)g_v)[n * 2 + 1]    = o1;
        ((float4*)g_agg2)[n * 2]     = o0;   // self-loop seed
        ((float4*)g_agg2)[n * 2 + 1] = o1;
    }
    gsync(nb);

    // ================= Phase E: edge scatter agg2 += v[src] ===================
    for (int e = gtid; e < E; e += T) {
        int2 p = g_edge[e];
        float4 a = __ldg((const float4*)(g_v + (size_t)p.x * HH));
        float4 b = __ldg((const float4*)(g_v + (size_t)p.x * HH) + 1);
        red_add_v4(g_agg2 + (size_t)p.y * HH,     a);
        red_add_v4(g_agg2 + (size_t)p.y * HH + 4, b);
    }
    gsync(nb);

    // ================= Phase F: GEMM2 + relu + size_factors; reset degi =======
    for (int i = tid; i < DD * HH; i += TPB) s_w[i] = W2[i];
    for (int i = tid; i < DD; i += TPB)      s_w[DD * HH + i] = b2[i];
    __syncthreads();

    for (int n = gwarp; n < N; n += W) {
        float di  = rsqrtf(1.0f + (float)g_degi[n]);
        float myv = g_agg2[(size_t)n * HH + (lane & 7)] * di;
        float a[HH];
#pragma unroll
        for (int h = 0; h < HH; h++) a[h] = __shfl_sync(0xffffffffu, myv, h);
        float s = sf[n];
#pragma unroll
        for (int j = 0; j < 4; j++) {
            int d4 = lane + 32 * j;
            float4 acc = ((const float4*)&s_w[DD * HH])[d4];
#pragma unroll
            for (int h = 0; h < HH; h++) {
                float4 w = ((const float4*)s_w)[h * (DD / 4) + d4];
                acc.x = fmaf(a[h], w.x, acc.x);
                acc.y = fmaf(a[h], w.y, acc.y);
                acc.z = fmaf(a[h], w.z, acc.z);
                acc.w = fmaf(a[h], w.w, acc.w);
            }
            acc.x = fmaxf(acc.x, 0.f) * s;
            acc.y = fmaxf(acc.y, 0.f) * s;
            acc.z = fmaxf(acc.z, 0.f) * s;
            acc.w = fmaxf(acc.w, 0.f) * s;
            ((float4*)out)[(size_t)n * (DD / 4) + d4] = acc;
        }
        if (lane == 0) g_degi[n] = 0;   // restore zero-invariant for next call
    }
}

// ---------------- launch -------------------------------------------------------
extern "C" void kernel_launch(void* const* d_in, const int* in_sizes, int n_in,
                              void* d_out, int out_size) {
    const float* x     = (const float*)d_in[0];
    const float* sf    = (const float*)d_in[1];
    const float* W1    = (const float*)d_in[2];
    const float* b1    = (const float*)d_in[3];
    const float* gamma = (const float*)d_in[4];
    const float* beta  = (const float*)d_in[5];
    const float* W2    = (const float*)d_in[6];
    const float* b2    = (const float*)d_in[7];
    const int*   ei    = (const int*)d_in[8];
    float* out = (float*)d_out;

    int N = in_sizes[0] / DD;
    int E = in_sizes[8] / 2;
    if (N > MAXN) N = MAXN;
    if (E > MAXE) E = MAXE;

    // Size the persistent grid to exactly the co-resident capacity (cached).
    static int s_grid = 0;
    if (s_grid == 0) {
        int nsm = 0, bps = 0;
        cudaDeviceGetAttribute(&nsm, cudaDevAttrMultiProcessorCount, 0);
        cudaOccupancyMaxActiveBlocksPerMultiprocessor(&bps, k_fused, TPB, 0);
        if (nsm <= 0) nsm = 148;
        if (bps <= 0) bps = 2;
        s_grid = nsm * bps;
    }
    unsigned nb = (unsigned)s_grid;
    k_fused<<<s_grid, TPB>>>(x, sf, W1, b1, gamma, beta, W2, b2, ei, out,
                             N, E, nb);
}

// round 5
// speedup vs baseline: 1.3767x; 1.0803x over previous
#include <cuda_runtime.h>
#include <stdint.h>

#define DD 512
#define HH 8
#define MAXN 50048
#define MAXE 800000
#define LN_EPS 1e-5f
#define TPB 256

// ---------------- scratch (device globals; zero-initialized at load) -----------
__device__ __align__(16) int   g_degi[MAXN];     // invariant: zero at call entry
__device__ __align__(16) float g_u   [MAXN * HH];
__device__ __align__(16) float g_agg1[MAXN * HH];
__device__ __align__(16) float g_v   [MAXN * HH];
__device__ __align__(16) float g_agg2[MAXN * HH];
__device__ __align__(16) int2  g_edge[MAXE];
__device__ unsigned g_bar;                        // monotonic, never reset

// ---------------- helpers ------------------------------------------------------
__device__ __forceinline__ void red_add_v4(float* addr, float4 v) {
    asm volatile("red.global.add.v4.f32 [%0], {%1,%2,%3,%4};"
                 :: "l"(addr), "f"(v.x), "f"(v.y), "f"(v.z), "f"(v.w)
                 : "memory");
}

// Monotonic grid barrier: safe across graph replays (no reset needed).
__device__ __forceinline__ void gsync(unsigned nb) {
    __syncthreads();
    if (threadIdx.x == 0) {
        __threadfence();
        unsigned my = atomicAdd(&g_bar, 1u);
        unsigned target = my - (my % nb) + nb;
        while ((int)(*(volatile unsigned*)&g_bar - target) < 0) __nanosleep(64);
        __threadfence();
    }
    __syncthreads();
}

// ---------------- the single persistent kernel ---------------------------------
__global__ void __launch_bounds__(TPB, 4)
k_fused(const float* __restrict__ x,
        const float* __restrict__ sf,
        const float* __restrict__ W1,
        const float* __restrict__ b1,
        const float* __restrict__ gamma,
        const float* __restrict__ beta,
        const float* __restrict__ W2,
        const float* __restrict__ b2,
        const int*   __restrict__ ei,
        float* __restrict__ out,
        int N, int E, unsigned nb) {
    const int tid   = threadIdx.x;
    const int gtid  = blockIdx.x * TPB + tid;
    const int T     = gridDim.x * TPB;
    const int lane  = tid & 31;
    const int gwarp = gtid >> 5;
    const int W     = T >> 5;

    // Phase A: W1 transposed, s_w[h*DD + c] (16 KB). Phase F: W2 | b2 (18 KB).
    __shared__ float s_w[DD * HH + DD];
    __shared__ int   s_is64;

    // ---- prologue: stage W1 transposed + int64/int32 detection ----
    for (int i = tid; i < DD * HH; i += TPB) {
        int c = i >> 3, h = i & 7;           // W1 is [DD][HH] row-major
        s_w[h * DD + c] = W1[i];
    }
    if (tid == 0) {
        int f = 1;
        int lim = 2 * E < 32 ? 2 * E : 32;
        for (int w = 1; w < lim; w += 2)
            if (ei[w] != 0) { f = 0; break; }
        s_is64 = f;
    }
    __syncthreads();

    // ================= Phase A: edge prep + raw GEMM1 (independent) ==========
    {
        const int is64 = s_is64;
        for (int e = gtid; e < E; e += T) {
            int src, dst;
            if (is64) {
                src = ((const int2*)ei)[e].x;
                dst = ((const int2*)ei)[(size_t)E + e].x;
            } else {
                src = ei[e];
                dst = ei[E + e];
            }
            g_edge[e] = make_int2(src, dst);
            atomicAdd(&g_degi[dst], 1);
        }
    }
    // raw u = x @ W1; warp per 4 nodes (W smem reads amortized over 4 FMAs)
    for (int n0 = gwarp * 4; n0 < N; n0 += W * 4) {
        const float* xp[4];
#pragma unroll
        for (int i = 0; i < 4; i++) {
            int n = n0 + i; if (n >= N) n = N - 1;
            xp[i] = x + (size_t)n * DD;
        }
        float acc[4][HH];
#pragma unroll
        for (int i = 0; i < 4; i++)
#pragma unroll
            for (int h = 0; h < HH; h++) acc[i][h] = 0.f;

#pragma unroll 4
        for (int it = 0; it < 16; it++) {
            int c = lane + it * 32;
            float xv0 = __ldcs(xp[0] + c);
            float xv1 = __ldcs(xp[1] + c);
            float xv2 = __ldcs(xp[2] + c);
            float xv3 = __ldcs(xp[3] + c);
#pragma unroll
            for (int h = 0; h < HH; h++) {
                float wv = s_w[h * DD + c];   // conflict-free scalar LDS
                acc[0][h] = fmaf(xv0, wv, acc[0][h]);
                acc[1][h] = fmaf(xv1, wv, acc[1][h]);
                acc[2][h] = fmaf(xv2, wv, acc[2][h]);
                acc[3][h] = fmaf(xv3, wv, acc[3][h]);
            }
        }
#pragma unroll
        for (int off = 16; off; off >>= 1)
#pragma unroll
            for (int i = 0; i < 4; i++)
#pragma unroll
                for (int h = 0; h < HH; h++)
                    acc[i][h] += __shfl_xor_sync(0xffffffffu, acc[i][h], off);
        // lanes 0..3 write nodes n0..n0+3
        if (lane < 4 && n0 + lane < N) {
            int n = n0 + lane;
            ((float4*)g_u)[n * 2]     = make_float4(acc[lane][0], acc[lane][1],
                                                    acc[lane][2], acc[lane][3]);
            ((float4*)g_u)[n * 2 + 1] = make_float4(acc[lane][4], acc[lane][5],
                                                    acc[lane][6], acc[lane][7]);
        }
    }
    gsync(nb);

    // ================= Phase B: u *= dinv; seed agg1 ==========================
    for (int n = gtid; n < N; n += T) {
        float di = rsqrtf(1.0f + (float)g_degi[n]);
        float4 a = ((float4*)g_u)[n * 2];
        float4 b = ((float4*)g_u)[n * 2 + 1];
        a.x *= di; a.y *= di; a.z *= di; a.w *= di;
        b.x *= di; b.y *= di; b.z *= di; b.w *= di;
        ((float4*)g_u)[n * 2]        = a;
        ((float4*)g_u)[n * 2 + 1]    = b;
        ((float4*)g_agg1)[n * 2]     = a;   // self-loop seed
        ((float4*)g_agg1)[n * 2 + 1] = b;
    }
    gsync(nb);

    // ================= Phase C: edge scatter agg1 += u[src] ===================
    for (int e = gtid; e < E; e += T) {
        int2 p = g_edge[e];
        float4 a = __ldg((const float4*)(g_u + (size_t)p.x * HH));
        float4 b = __ldg((const float4*)(g_u + (size_t)p.x * HH) + 1);
        red_add_v4(g_agg1 + (size_t)p.y * HH,     a);
        red_add_v4(g_agg1 + (size_t)p.y * HH + 4, b);
    }
    gsync(nb);

    // ================= Phase D: bias + LN + ReLU + dinv; seed agg2 ============
    for (int n = gtid; n < N; n += T) {
        float di = rsqrtf(1.0f + (float)g_degi[n]);
        float4 p0 = ((const float4*)g_agg1)[n * 2];
        float4 p1 = ((const float4*)g_agg1)[n * 2 + 1];
        float h[HH] = {p0.x, p0.y, p0.z, p0.w, p1.x, p1.y, p1.z, p1.w};
        float mu = 0.f;
#pragma unroll
        for (int k = 0; k < HH; k++) { h[k] = h[k] * di + __ldg(&b1[k]); mu += h[k]; }
        mu *= 0.125f;
        float var = 0.f;
#pragma unroll
        for (int k = 0; k < HH; k++) { float d = h[k] - mu; var += d * d; }
        var *= 0.125f;
        float r = rsqrtf(var + LN_EPS);
        float v[HH];
#pragma unroll
        for (int k = 0; k < HH; k++) {
            float hn = (h[k] - mu) * r * __ldg(&gamma[k]) + __ldg(&beta[k]);
            v[k] = fmaxf(hn, 0.f) * di;
        }
        float4 o0 = make_float4(v[0], v[1], v[2], v[3]);
        float4 o1 = make_float4(v[4], v[5], v[6], v[7]);
        ((float4*)g_v)[n * 2]        = o0;
        ((float4*)g_v)[n * 2 + 1]    = o1;
        ((float4*)g_agg2)[n * 2]     = o0;   // self-loop seed
        ((float4*)g_agg2)[n * 2 + 1] = o1;
    }
    gsync(nb);

    // ================= Phase E: edge scatter agg2 += v[src] ===================
    for (int e = gtid; e < E; e += T) {
        int2 p = g_edge[e];
        float4 a = __ldg((const float4*)(g_v + (size_t)p.x * HH));
        float4 b = __ldg((const float4*)(g_v + (size_t)p.x * HH) + 1);
        red_add_v4(g_agg2 + (size_t)p.y * HH,     a);
        red_add_v4(g_agg2 + (size_t)p.y * HH + 4, b);
    }
    gsync(nb);

    // ================= Phase F: GEMM2 + relu + sf; warp per 4 nodes ===========
    for (int i = tid; i < DD * HH; i += TPB) s_w[i] = W2[i];
    for (int i = tid; i < DD; i += TPB)      s_w[DD * HH + i] = b2[i];
    __syncthreads();

    for (int n0 = gwarp * 4; n0 < N; n0 += W * 4) {
        // coalesced: lane l serves node n0+(l>>3), feature (l&7)
        int nl = n0 + (lane >> 3); if (nl >= N) nl = N - 1;
        float di  = rsqrtf(1.0f + (float)g_degi[nl]);
        float myv = g_agg2[(size_t)nl * HH + (lane & 7)] * di;
        float sfv = sf[nl];
        float a[4][HH];
        float s[4];
#pragma unroll
        for (int i = 0; i < 4; i++) {
            s[i] = __shfl_sync(0xffffffffu, sfv, i * 8);
#pragma unroll
            for (int h = 0; h < HH; h++)
                a[i][h] = __shfl_sync(0xffffffffu, myv, i * 8 + h);
        }
#pragma unroll
        for (int j = 0; j < 4; j++) {
            int d4 = lane + 32 * j;
            float4 bias = ((const float4*)&s_w[DD * HH])[d4];
            float4 acc0 = bias, acc1 = bias, acc2 = bias, acc3 = bias;
#pragma unroll
            for (int h = 0; h < HH; h++) {
                float4 w = ((const float4*)s_w)[h * (DD / 4) + d4];
                acc0.x = fmaf(a[0][h], w.x, acc0.x); acc0.y = fmaf(a[0][h], w.y, acc0.y);
                acc0.z = fmaf(a[0][h], w.z, acc0.z); acc0.w = fmaf(a[0][h], w.w, acc0.w);
                acc1.x = fmaf(a[1][h], w.x, acc1.x); acc1.y = fmaf(a[1][h], w.y, acc1.y);
                acc1.z = fmaf(a[1][h], w.z, acc1.z); acc1.w = fmaf(a[1][h], w.w, acc1.w);
                acc2.x = fmaf(a[2][h], w.x, acc2.x); acc2.y = fmaf(a[2][h], w.y, acc2.y);
                acc2.z = fmaf(a[2][h], w.z, acc2.z); acc2.w = fmaf(a[2][h], w.w, acc2.w);
                acc3.x = fmaf(a[3][h], w.x, acc3.x); acc3.y = fmaf(a[3][h], w.y, acc3.y);
                acc3.z = fmaf(a[3][h], w.z, acc3.z); acc3.w = fmaf(a[3][h], w.w, acc3.w);
            }
            float4 r0 = make_float4(fmaxf(acc0.x,0.f)*s[0], fmaxf(acc0.y,0.f)*s[0],
                                    fmaxf(acc0.z,0.f)*s[0], fmaxf(acc0.w,0.f)*s[0]);
            float4 r1 = make_float4(fmaxf(acc1.x,0.f)*s[1], fmaxf(acc1.y,0.f)*s[1],
                                    fmaxf(acc1.z,0.f)*s[1], fmaxf(acc1.w,0.f)*s[1]);
            float4 r2 = make_float4(fmaxf(acc2.x,0.f)*s[2], fmaxf(acc2.y,0.f)*s[2],
                                    fmaxf(acc2.z,0.f)*s[2], fmaxf(acc2.w,0.f)*s[2]);
            float4 r3 = make_float4(fmaxf(acc3.x,0.f)*s[3], fmaxf(acc3.y,0.f)*s[3],
                                    fmaxf(acc3.z,0.f)*s[3], fmaxf(acc3.w,0.f)*s[3]);
            if (n0 + 0 < N) ((float4*)out)[(size_t)(n0+0) * (DD/4) + d4] = r0;
            if (n0 + 1 < N) ((float4*)out)[(size_t)(n0+1) * (DD/4) + d4] = r1;
            if (n0 + 2 < N) ((float4*)out)[(size_t)(n0+2) * (DD/4) + d4] = r2;
            if (n0 + 3 < N) ((float4*)out)[(size_t)(n0+3) * (DD/4) + d4] = r3;
        }
        if (lane < 4 && n0 + lane < N) g_degi[n0 + lane] = 0;  // restore invariant
    }
}

// ---------------- launch -------------------------------------------------------
extern "C" void kernel_launch(void* const* d_in, const int* in_sizes, int n_in,
                              void* d_out, int out_size) {
    const float* x     = (const float*)d_in[0];
    const float* sf    = (const float*)d_in[1];
    const float* W1    = (const float*)d_in[2];
    const float* b1    = (const float*)d_in[3];
    const float* gamma = (const float*)d_in[4];
    const float* beta  = (const float*)d_in[5];
    const float* W2    = (const float*)d_in[6];
    const float* b2    = (const float*)d_in[7];
    const int*   ei    = (const int*)d_in[8];
    float* out = (float*)d_out;

    int N = in_sizes[0] / DD;
    int E = in_sizes[8] / 2;
    if (N > MAXN) N = MAXN;
    if (E > MAXE) E = MAXE;

    static int s_grid = 0;
    if (s_grid == 0) {
        int nsm = 0, bps = 0;
        cudaDeviceGetAttribute(&nsm, cudaDevAttrMultiProcessorCount, 0);
        cudaOccupancyMaxActiveBlocksPerMultiprocessor(&bps, k_fused, TPB, 0);
        if (nsm <= 0) nsm = 148;
        if (bps <= 0) bps = 2;
        s_grid = nsm * bps;
    }
    unsigned nb = (unsigned)s_grid;
    k_fused<<<s_grid, TPB>>>(x, sf, W1, b1, gamma, beta, W2, b2, ei, out,
                             N, E, nb);
}